// round 10
// baseline (speedup 1.0000x reference)
#include <cuda_runtime.h>
#include <cstdint>
#include <cstddef>

#define B_ 32
#define S_ 4096
#define E_ 1024
#define H_ 16
#define HB 8             // heads per block
#define D_ 64
#define NC 16            // chunks over s (256 rows each)
#define RPB 4            // rows per batch
#define NBAT 64          // 256 / RPB
#define NST 5            // cp.async ring stages
#define L2E 1.4426950408889634f

// ---------------- static scratch ----------------
__device__ float g_q[B_ * E_];
__device__ float g_qk[B_ * H_ * E_];
__device__ float g_ctxp[(size_t)NC * B_ * H_ * E_];   // unnormalized ctx per chunk
__device__ float g_m[NC * B_ * H_];
__device__ float g_d[NC * B_ * H_];

typedef unsigned long long u64;

__device__ __forceinline__ u64 pack2(float x, float y) {
    u64 p;
    asm("mov.b64 %0, {%1, %2};" : "=l"(p) : "f"(x), "f"(y));
    return p;
}
__device__ __forceinline__ void unpack2(u64 p, float& x, float& y) {
    asm("mov.b64 {%0, %1}, %2;" : "=f"(x), "=f"(y) : "l"(p));
}
__device__ __forceinline__ u64 ffma2(u64 a, u64 b, u64 c) {
    u64 d;
    asm("fma.rn.f32x2 %0, %1, %2, %3;" : "=l"(d) : "l"(a), "l"(b), "l"(c));
    return d;
}
__device__ __forceinline__ u64 fmul2(u64 a, u64 b) {
    u64 d;
    asm("mul.rn.f32x2 %0, %1, %2;" : "=l"(d) : "l"(a), "l"(b));
    return d;
}
__device__ __forceinline__ u64 fadd2(u64 a, u64 b) {
    u64 d;
    asm("add.rn.f32x2 %0, %1, %2;" : "=l"(d) : "l"(a), "l"(b));
    return d;
}
__device__ __forceinline__ void cp16(uint32_t dst_smem, const void* src) {
    asm volatile("cp.async.cg.shared.global [%0], [%1], 16;" :: "r"(dst_smem), "l"(src));
}
__device__ __forceinline__ void cp_commit() { asm volatile("cp.async.commit_group;"); }
template <int N>
__device__ __forceinline__ void cp_wait() { asm volatile("cp.async.wait_group %0;" :: "n"(N)); }

// ---------------- K1: q = seq1@Wq + bq  (1 b per block, 128 blocks) ----------------
// grid (4 jt, 32 b) block 256
__global__ void k_qproj(const float* __restrict__ seq1, const float* __restrict__ Wq,
                        const float* __restrict__ bq) {
    int b = blockIdx.y;
    int j = blockIdx.x * 256 + threadIdx.x;
    __shared__ __align__(16) float s1[E_];
    ((float4*)s1)[threadIdx.x] = ((const float4*)(seq1 + (size_t)b * E_))[threadIdx.x];
    __syncthreads();
    float a0 = 0.f, a1 = 0.f, a2 = 0.f, a3 = 0.f;
#pragma unroll 4
    for (int e = 0; e < E_; e += 4) {
        a0 = fmaf(s1[e + 0], Wq[(size_t)(e + 0) * E_ + j], a0);
        a1 = fmaf(s1[e + 1], Wq[(size_t)(e + 1) * E_ + j], a1);
        a2 = fmaf(s1[e + 2], Wq[(size_t)(e + 2) * E_ + j], a2);
        a3 = fmaf(s1[e + 3], Wq[(size_t)(e + 3) * E_ + j], a3);
    }
    g_q[b * E_ + j] = ((a0 + a1) + (a2 + a3)) + bq[j];
}

// ---------------- K2: qk[b][h][e] = (Σ_d q[b][h*64+d]·Wk[e][h*64+d]) * 0.125 ----------------
// grid (16 h, 16 et) block 256: thread = e_local(64) x bg(4, 8 b each)
__global__ void k_qk(const float* __restrict__ Wk) {
    int h = blockIdx.x;
    int e = blockIdx.y * 64 + (threadIdx.x & 63);
    int bg = threadIdx.x >> 6;
    __shared__ __align__(16) float2 sq[B_][D_ / 2];
    for (int i = threadIdx.x; i < B_ * (D_ / 2); i += 256) {
        int b = i >> 5, dp = i & 31;
        sq[b][dp] = ((const float2*)(g_q + b * E_ + h * D_))[dp];
    }
    __syncthreads();
    float2 wk[D_ / 2];
    const float2* wrow = (const float2*)(Wk + (size_t)e * E_ + h * D_);
#pragma unroll
    for (int i = 0; i < D_ / 2; i++) wk[i] = wrow[i];
#pragma unroll
    for (int bb = 0; bb < 8; bb++) {
        int b = bg * 8 + bb;
        float ax = 0.f, ay = 0.f;
#pragma unroll
        for (int i = 0; i < D_ / 2; i++) {
            float2 qv = sq[b][i];
            ax = fmaf(wk[i].x, qv.x, ax);
            ay = fmaf(wk[i].y, qv.y, ay);
        }
        g_qk[(b * H_ + h) * E_ + e] = (ax + ay) * 0.125f;
    }
}

// ---------------- pad kernel (keeps ncu sample index on k_fused) ----------------
__global__ void k_pad() {}

// ---------------- K3: fused scores + online softmax + ctx (8 heads/block) ----------------
// grid (2 hb, NC, B_) block 512, 2 blocks/SM
// thread: hg = tid>>8 (0..1) -> heads hb*8+hg*4+j ; eidx = tid&255 -> float4 at eidx*4
// dyn smem: sx[NST][RPB][1024] 80KB + sred[4][8][9] 1152B
__global__ void __launch_bounds__(512, 2) k_fused(const float* __restrict__ seq2,
                                                  const int* __restrict__ mask) {
    extern __shared__ __align__(16) char dyn[];
    float* sx   = (float*)dyn;                          // [NST][RPB][1024]
    float* sred = (float*)(dyn + NST * RPB * 4096);     // [4][8][9]
    __shared__ __align__(16) float sw_[RPB][HB];
    __shared__ __align__(16) float sfac[HB];
    __shared__ float sm_m[HB], sm_d[HB];
    __shared__ uint32_t sball[8];

    int hb = blockIdx.x;
    int chunk = blockIdx.y;
    int b = blockIdx.z;
    int s0 = chunk * 256;
    int tid = threadIdx.x;
    int hg = tid >> 8;              // 0..1
    int eidx = tid & 255;           // 0..255
    int lane = tid & 31;

    if (tid < 256) {
        int mm = mask[b * S_ + s0 + tid];
        uint32_t bal = __ballot_sync(0xffffffffu, mm != 0);
        if ((tid & 31) == 0) sball[tid >> 5] = bal;
    }
    if (tid < HB) { sm_m[tid] = -1e30f; sm_d[tid] = 0.f; }

    // qk regs: 4 heads x 4 floats
    u64 qk2[4][2];
#pragma unroll
    for (int j = 0; j < 4; j++) {
        const float* qb = g_qk + ((size_t)b * H_ + hb * HB + hg * 4 + j) * E_;
        float4 v = *(const float4*)(qb + eidx * 4);
        qk2[j][0] = pack2(v.x, v.y);
        qk2[j][1] = pack2(v.z, v.w);
    }

    u64 ctx[4][2];
#pragma unroll
    for (int j = 0; j < 4; j++) {
        ctx[j][0] = pack2(0.f, 0.f);
        ctx[j][1] = pack2(0.f, 0.f);
    }

    uint32_t sx_addr = (uint32_t)__cvta_generic_to_shared(sx);
    const float* base = seq2 + ((size_t)b * S_ + s0) * E_;
    int srow = tid >> 7;            // 0..3 staging row
    int scol = tid & 127;           // 8 floats/thread/row

    __syncthreads();                // sball / sm_* visible

    // prologue: prefetch batches 0..3 (4 groups in flight)
#pragma unroll
    for (int nb = 0; nb < 4; nb++) {
        uint32_t flN = (sball[0] >> (nb * 4)) & 0xF;
        if ((flN >> srow) & 1) {
            const float* src = base + ((size_t)nb * RPB + srow) * E_ + scol * 8;
            uint32_t dst = sx_addr + (uint32_t)(nb * RPB + srow) * 4096 + scol * 32;
            cp16(dst, src);
            cp16(dst + 16, src + 4);
        }
        cp_commit();
    }

    for (int bat = 0; bat < NBAT; bat++) {
        cp_wait<3>();
        __syncthreads();            // sync1: batch `bat` ready; ring slot (bat+4)%5 free

        {   // issue bat+4 AFTER the barrier (slot-reuse safe); one commit per iter
            int nb = bat + 4;
            if (nb < NBAT) {
                uint32_t flN = (sball[nb >> 3] >> ((nb & 7) * 4)) & 0xF;
                if ((flN >> srow) & 1) {
                    const float* src = base + ((size_t)nb * RPB + srow) * E_ + scol * 8;
                    uint32_t dst = sx_addr + (uint32_t)((nb % NST) * RPB + srow) * 4096 + scol * 32;
                    cp16(dst, src);
                    cp16(dst + 16, src + 4);
                }
            }
            cp_commit();
        }

        uint32_t fl = (sball[bat >> 3] >> ((bat & 7) * 4)) & 0xF;
        if (fl == 0) continue;      // block-uniform skip

        const float* xs = sx + (bat % NST) * (RPB * 1024);

        // ---- Phase A: dot partials + in-register butterfly reduction ----
#pragma unroll
        for (int r = 0; r < RPB; r++) {
            if ((fl >> r) & 1) {
                float4 xv = *(const float4*)(xs + r * 1024 + eidx * 4);
                u64 x0 = pack2(xv.x, xv.y), x1 = pack2(xv.z, xv.w);
                float pj[4];
#pragma unroll
                for (int j = 0; j < 4; j++) {
                    u64 a = fmul2(qk2[j][0], x0);
                    a = ffma2(qk2[j][1], x1, a);
                    float ax, ay;
                    unpack2(a, ax, ay);
                    pj[j] = ax + ay;
                }
                u64 p01 = pack2(pj[0], pj[1]);
                u64 p23 = pack2(pj[2], pj[3]);
                // xor1: head split (even lanes -> heads {0,1}, odd -> {2,3})
                u64 snd = (lane & 1) ? p01 : p23;
                u64 rcv = __shfl_xor_sync(0xffffffffu, snd, 1);
                u64 kp  = (lane & 1) ? p23 : p01;
                u64 s2  = fadd2(kp, rcv);
                // xor2: f32x2 half split
                u64 o2 = __shfl_xor_sync(0xffffffffu, s2, 2);
                float sxl, sxh, oxl, oxh;
                unpack2(s2, sxl, sxh);
                unpack2(o2, oxl, oxh);
                float val = (lane & 2) ? (sxh + oxh) : (sxl + oxl);
                // xor4/8/16: full warp sum (head preserved by lane&3)
                val += __shfl_xor_sync(0xffffffffu, val, 4);
                val += __shfl_xor_sync(0xffffffffu, val, 8);
                val += __shfl_xor_sync(0xffffffffu, val, 16);
                if (lane < 4) {
                    int jm = ((lane & 1) << 1) | ((lane >> 1) & 1);
                    sred[(r * 8 + hg * 4 + jm) * 9 + ((tid >> 5) & 7)] = val;
                }
            }
        }
        __syncthreads();            // sync2: sred ready

        // ---- stage2 + online softmax: one warp per head ----
        if (tid < 256) {
            int h = tid >> 5;                 // 0..7 local head (warp per head)
            int r = (lane >> 3) & 3;
            int q = lane & 7;
            float s = sred[(r * 8 + h) * 9 + q];
            s += __shfl_xor_sync(0xffffffffu, s, 1);
            s += __shfl_xor_sync(0xffffffffu, s, 2);
            s += __shfl_xor_sync(0xffffffffu, s, 4);       // full score(r,h)
            bool act = (fl >> r) & 1;
            float sv = act ? s : -1e30f;
            float m0 = sm_m[h];
            float t = sv;
            t = fmaxf(t, __shfl_xor_sync(0xffffffffu, t, 8));
            t = fmaxf(t, __shfl_xor_sync(0xffffffffu, t, 16));   // max over r
            float nm = fmaxf(t, m0);
            float fac = exp2f((m0 - nm) * L2E);
            float w = act ? exp2f((s - nm) * L2E) : 0.f;
            if (q == 0) sw_[r][h] = w;
            float ws = w;
            ws += __shfl_xor_sync(0xffffffffu, ws, 8);
            ws += __shfl_xor_sync(0xffffffffu, ws, 16);
            if (q == 0 && r == 0) {
                sfac[h] = fac;
                sm_m[h] = nm;
                sm_d[h] = fmaf(fac, sm_d[h], ws);
            }
        }
        __syncthreads();            // sync3: sw_/sfac ready

        // ---- Phase B: rescale + weighted accumulate ----
        {
            float4 fv = *(const float4*)&sfac[hg * 4];
            u64 f2[4] = {pack2(fv.x, fv.x), pack2(fv.y, fv.y),
                         pack2(fv.z, fv.z), pack2(fv.w, fv.w)};
#pragma unroll
            for (int j = 0; j < 4; j++) {
                ctx[j][0] = fmul2(ctx[j][0], f2[j]);
                ctx[j][1] = fmul2(ctx[j][1], f2[j]);
            }
#pragma unroll
            for (int r = 0; r < RPB; r++) {
                if (!((fl >> r) & 1)) continue;
                float4 wv = *(const float4*)&sw_[r][hg * 4];
                u64 w2[4] = {pack2(wv.x, wv.x), pack2(wv.y, wv.y),
                             pack2(wv.z, wv.z), pack2(wv.w, wv.w)};
                float4 xv = *(const float4*)(xs + r * 1024 + eidx * 4);
                u64 x0 = pack2(xv.x, xv.y), x1 = pack2(xv.z, xv.w);
#pragma unroll
                for (int j = 0; j < 4; j++) {
                    ctx[j][0] = ffma2(w2[j], x0, ctx[j][0]);
                    ctx[j][1] = ffma2(w2[j], x1, ctx[j][1]);
                }
            }
        }
    }

    // epilogue: unnormalized ctx + per-chunk (m, d)
#pragma unroll
    for (int j = 0; j < 4; j++) {
        float* dst = g_ctxp +
            (((size_t)chunk * B_ + b) * H_ + hb * HB + hg * 4 + j) * E_ + eidx * 4;
        float x0, y0, x1, y1;
        unpack2(ctx[j][0], x0, y0);
        unpack2(ctx[j][1], x1, y1);
        *(float4*)dst = make_float4(x0, y0, x1, y1);
    }
    if (tid < HB) {
        g_m[(chunk * B_ + b) * H_ + hb * HB + tid] = sm_m[tid];
        g_d[(chunk * B_ + b) * H_ + hb * HB + tid] = sm_d[tid];
    }
}

// ---------------- K4: weighted combine + out = ctx@Wv + bv (1 b per block) ----------------
// grid (16 h, 32 b) block 256
__global__ void k_out(const float* __restrict__ Wv, const float* __restrict__ bv,
                      float* __restrict__ out) {
    int h = blockIdx.x;
    int b = blockIdx.y;
    int tid = threadIdx.x;
    int n = tid & 63;
    int qq = tid >> 6;

    __shared__ __align__(16) float sc[E_];
    __shared__ float smd[2][NC];
    __shared__ float swt[NC];

    if (tid < NC) {
        smd[0][tid] = g_m[(tid * B_ + b) * H_ + h];
        smd[1][tid] = g_d[(tid * B_ + b) * H_ + h];
    }
    __syncthreads();
    if (tid == 0) {
        float M = -1e30f;
#pragma unroll
        for (int c = 0; c < NC; c++) M = fmaxf(M, smd[0][c]);
        float Dn = 0.f;
        float t[NC];
#pragma unroll
        for (int c = 0; c < NC; c++) {
            float e = exp2f((smd[0][c] - M) * L2E);
            t[c] = e;
            Dn = fmaf(e, smd[1][c], Dn);
        }
        float invD = 1.0f / Dn;
#pragma unroll
        for (int c = 0; c < NC; c++) swt[c] = t[c] * invD;
    }
    __syncthreads();

    {
        float4 a = make_float4(0.f, 0.f, 0.f, 0.f);
#pragma unroll
        for (int c = 0; c < NC; c++) {
            float w = swt[c];
            float4 v = ((const float4*)(g_ctxp + (((size_t)c * B_ + b) * H_ + h) * E_))[tid];
            a.x = fmaf(w, v.x, a.x);
            a.y = fmaf(w, v.y, a.y);
            a.z = fmaf(w, v.z, a.z);
            a.w = fmaf(w, v.w, a.w);
        }
        ((float4*)sc)[tid] = a;
    }
    __syncthreads();

    int c = h * D_ + n;
    float acc = 0.f;
#pragma unroll 4
    for (int e = 0; e < 256; e++)
        acc = fmaf(sc[qq * 256 + e], Wv[(size_t)(qq * 256 + e) * E_ + c], acc);

    __shared__ float part[4][64];
    part[qq][n] = acc;
    __syncthreads();
    if (tid < 64)
        out[(size_t)b * E_ + h * D_ + tid] =
            ((part[0][tid] + part[1][tid]) + (part[2][tid] + part[3][tid])) + bv[h * D_ + tid];
}

// ---------------- launch ----------------
extern "C" void kernel_launch(void* const* d_in, const int* in_sizes, int n_in,
                              void* d_out, int out_size) {
    const float* seq1 = (const float*)d_in[0];
    const float* seq2 = (const float*)d_in[1];
    const int*   mask = (const int*)d_in[2];
    const float* Wq   = (const float*)d_in[3];
    const float* bq   = (const float*)d_in[4];
    const float* Wk   = (const float*)d_in[5];
    // d_in[6] = bk dropped (softmax-invariant uniform shift)
    const float* Wv   = (const float*)d_in[7];
    const float* bv   = (const float*)d_in[8];
    float* out = (float*)d_out;

    const int dynBytes = NST * RPB * 4096 + 4 * 8 * 9 * 4;   // 80KB + 1152B
    cudaFuncSetAttribute(k_fused, cudaFuncAttributeMaxDynamicSharedMemorySize, dynBytes);

    k_qproj<<<dim3(4, B_), 256>>>(seq1, Wq, bq);
    k_qk<<<dim3(H_, 16), 256>>>(Wk);
    k_pad<<<1, 32>>>();
    k_fused<<<dim3(2, NC, B_), 512, dynBytes>>>(seq2, mask);
    k_out<<<dim3(H_, B_), 256>>>(Wv, bv, out);
}

// round 13
// speedup vs baseline: 1.7505x; 1.7505x over previous
#include <cuda_runtime.h>
#include <cstdint>
#include <cstddef>

#define B_ 32
#define S_ 4096
#define E_ 1024
#define H_ 16
#define D_ 64
#define NC 16            // chunks over s (256 rows each)
#define RPB 8            // rows per batch
#define NBAT 32          // 256 / RPB
#define NST 4            // cp.async ring stages (32KB each)
#define L2E 1.4426950408889634f

// ---------------- static scratch ----------------
__device__ float g_q[B_ * E_];
__device__ float g_qk[B_ * H_ * E_];
__device__ float g_ctxp[(size_t)NC * B_ * H_ * E_];   // unnormalized ctx per chunk
__device__ float g_m[NC * B_ * H_];
__device__ float g_d[NC * B_ * H_];

typedef unsigned long long u64;

__device__ __forceinline__ u64 pack2(float x, float y) {
    u64 p;
    asm("mov.b64 %0, {%1, %2};" : "=l"(p) : "f"(x), "f"(y));
    return p;
}
__device__ __forceinline__ void unpack2(u64 p, float& x, float& y) {
    asm("mov.b64 {%0, %1}, %2;" : "=f"(x), "=f"(y) : "l"(p));
}
__device__ __forceinline__ u64 ffma2(u64 a, u64 b, u64 c) {
    u64 d;
    asm("fma.rn.f32x2 %0, %1, %2, %3;" : "=l"(d) : "l"(a), "l"(b), "l"(c));
    return d;
}
__device__ __forceinline__ u64 fmul2(u64 a, u64 b) {
    u64 d;
    asm("mul.rn.f32x2 %0, %1, %2;" : "=l"(d) : "l"(a), "l"(b));
    return d;
}
__device__ __forceinline__ void cp16(uint32_t dst_smem, const void* src) {
    asm volatile("cp.async.cg.shared.global [%0], [%1], 16;" :: "r"(dst_smem), "l"(src));
}
__device__ __forceinline__ void cp_commit() { asm volatile("cp.async.commit_group;"); }
template <int N>
__device__ __forceinline__ void cp_wait() { asm volatile("cp.async.wait_group %0;" :: "n"(N)); }

// ---------------- K1: q = seq1@Wq + bq  (1 b per block) ----------------
// grid (4 jt, 32 b) block 256
__global__ void k_qproj(const float* __restrict__ seq1, const float* __restrict__ Wq,
                        const float* __restrict__ bq) {
    int b = blockIdx.y;
    int j = blockIdx.x * 256 + threadIdx.x;
    __shared__ __align__(16) float s1[E_];
    ((float4*)s1)[threadIdx.x] = ((const float4*)(seq1 + (size_t)b * E_))[threadIdx.x];
    __syncthreads();
    float a0 = 0.f, a1 = 0.f, a2 = 0.f, a3 = 0.f;
#pragma unroll 4
    for (int e = 0; e < E_; e += 4) {
        a0 = fmaf(s1[e + 0], Wq[(size_t)(e + 0) * E_ + j], a0);
        a1 = fmaf(s1[e + 1], Wq[(size_t)(e + 1) * E_ + j], a1);
        a2 = fmaf(s1[e + 2], Wq[(size_t)(e + 2) * E_ + j], a2);
        a3 = fmaf(s1[e + 3], Wq[(size_t)(e + 3) * E_ + j], a3);
    }
    g_q[b * E_ + j] = ((a0 + a1) + (a2 + a3)) + bq[j];
}

// ---------------- K2: qk[b][h][e] = (Σ_d q[b][h*64+d]·Wk[e][h*64+d]) * 0.125 ----------------
// grid (16 h, 16 et) block 256: thread = e_local(64) x bg(4, 8 b each)
__global__ void k_qk(const float* __restrict__ Wk) {
    int h = blockIdx.x;
    int e = blockIdx.y * 64 + (threadIdx.x & 63);
    int bg = threadIdx.x >> 6;
    __shared__ __align__(16) float2 sq[B_][D_ / 2];
    for (int i = threadIdx.x; i < B_ * (D_ / 2); i += 256) {
        int b = i >> 5, dp = i & 31;
        sq[b][dp] = ((const float2*)(g_q + b * E_ + h * D_))[dp];
    }
    __syncthreads();
    float2 wk[D_ / 2];
    const float2* wrow = (const float2*)(Wk + (size_t)e * E_ + h * D_);
#pragma unroll
    for (int i = 0; i < D_ / 2; i++) wk[i] = wrow[i];
#pragma unroll
    for (int bb = 0; bb < 8; bb++) {
        int b = bg * 8 + bb;
        float ax = 0.f, ay = 0.f;
#pragma unroll
        for (int i = 0; i < D_ / 2; i++) {
            float2 qv = sq[b][i];
            ax = fmaf(wk[i].x, qv.x, ax);
            ay = fmaf(wk[i].y, qv.y, ay);
        }
        g_qk[(b * H_ + h) * E_ + e] = (ax + ay) * 0.125f;
    }
}

// ---------------- pad kernel (keeps ncu sample index on k_fused) ----------------
__global__ void k_pad() {}

// ---------------- K3: fused scores + online softmax + ctx ----------------
// grid (NC, B_) block 512
// thread: hg = tid&3 (heads hg*4+j), eidx = tid>>2 (8 floats at eidx*8; 128*8 = 1024 = E_)
// dyn smem: sx[NST][RPB][1024] 128KB + spart[128][68] 34KB
__global__ void __launch_bounds__(512, 1) k_fused(const float* __restrict__ seq2,
                                                  const int* __restrict__ mask) {
    extern __shared__ __align__(16) char dyn[];
    float* sx = (float*)dyn;                              // [NST][RPB][1024]
    float* spart = (float*)(dyn + NST * RPB * 4096);      // [rh=128][68]
    __shared__ float sscore[RPB][17];
    __shared__ __align__(16) float sw_[RPB][H_];
    __shared__ __align__(16) float sfac[H_];
    __shared__ float sm_m[H_], sm_d[H_];
    __shared__ uint32_t sball[8];

    int b = blockIdx.y;
    int chunk = blockIdx.x;
    int s0 = chunk * 256;
    int tid = threadIdx.x;
    int hg = tid & 3;
    int eidx = tid >> 2;            // 0..127, slice = 8 floats at eidx*8

    if (tid < 256) {
        int mm = mask[b * S_ + s0 + tid];
        uint32_t bal = __ballot_sync(0xffffffffu, mm != 0);
        if ((tid & 31) == 0) sball[tid >> 5] = bal;
    }
    if (tid < H_) { sm_m[tid] = -1e30f; sm_d[tid] = 0.f; }

    // qk regs: 4 heads x 8 e-floats (4 f32x2 each)
    u64 qk2[4][4];
#pragma unroll
    for (int j = 0; j < 4; j++) {
        const float4* p = (const float4*)(g_qk + ((size_t)b * H_ + hg * 4 + j) * E_ + eidx * 8);
        float4 v0 = p[0], v1 = p[1];
        qk2[j][0] = pack2(v0.x, v0.y);
        qk2[j][1] = pack2(v0.z, v0.w);
        qk2[j][2] = pack2(v1.x, v1.y);
        qk2[j][3] = pack2(v1.z, v1.w);
    }

    u64 ctx[4][4];
#pragma unroll
    for (int j = 0; j < 4; j++)
#pragma unroll
        for (int i = 0; i < 4; i++) ctx[j][i] = pack2(0.f, 0.f);

    uint32_t sx_addr = (uint32_t)__cvta_generic_to_shared(sx);
    const float* base = seq2 + ((size_t)b * S_ + s0) * E_;
    int srow = tid >> 6;            // 0..7 staging row
    int scol = tid & 63;            // 16 floats per thread per row

    __syncthreads();                // sball/sm_* visible

    // prologue: prefetch batches 0,1,2 into slots 0,1,2
#pragma unroll
    for (int nb = 0; nb < 3; nb++) {
        uint32_t flN = (sball[nb >> 2] >> ((nb & 3) * 8)) & 0xFF;
        if ((flN >> srow) & 1) {
            const float* src = base + ((size_t)nb * RPB + srow) * E_ + scol * 16;
            uint32_t dst = sx_addr + (uint32_t)(nb * RPB + srow) * 4096 + scol * 64;
#pragma unroll
            for (int k = 0; k < 4; k++) cp16(dst + k * 16, src + k * 4);
        }
        cp_commit();
    }

    for (int bat = 0; bat < NBAT; bat++) {
        cp_wait<2>();
        __syncthreads();            // sync1: batch `bat` ready; slot (bat+3)&3 free

        {   // issue bat+3 AFTER the barrier (slot-reuse safe); one commit per iter
            int nb = bat + 3;
            if (nb < NBAT) {
                uint32_t flN = (sball[nb >> 2] >> ((nb & 3) * 8)) & 0xFF;
                if ((flN >> srow) & 1) {
                    const float* src = base + ((size_t)nb * RPB + srow) * E_ + scol * 16;
                    uint32_t dst = sx_addr + (uint32_t)((nb & 3) * RPB + srow) * 4096 + scol * 64;
#pragma unroll
                    for (int k = 0; k < 4; k++) cp16(dst + k * 16, src + k * 4);
                }
            }
            cp_commit();
        }

        uint32_t fl = (sball[bat >> 2] >> ((bat & 3) * 8)) & 0xFF;
        if (fl == 0) continue;

        const float* xs = sx + (bat & 3) * (RPB * 1024);

        // ---- Phase A: per-head partial dots ----
#pragma unroll
        for (int r = 0; r < RPB; r++) {
            if ((fl >> r) & 1) {
                const float4* xr = (const float4*)(xs + r * 1024 + eidx * 8);
                float4 xa = xr[0], xb = xr[1];
                u64 x0 = pack2(xa.x, xa.y), x1 = pack2(xa.z, xa.w);
                u64 x2 = pack2(xb.x, xb.y), x3 = pack2(xb.z, xb.w);
                float part[4];
#pragma unroll
                for (int j = 0; j < 4; j++) {
                    u64 a = fmul2(qk2[j][0], x0);
                    a = ffma2(qk2[j][1], x1, a);
                    a = ffma2(qk2[j][2], x2, a);
                    a = ffma2(qk2[j][3], x3, a);
                    float ax, ay;
                    unpack2(a, ax, ay);
                    part[j] = ax + ay;
                }
#pragma unroll
                for (int j = 0; j < 4; j++)
                    part[j] += __shfl_xor_sync(0xffffffffu, part[j], 4);
                if ((tid & 4) == 0) {       // even eidx writes combined pair
                    int e2 = eidx >> 1;     // 0..63
#pragma unroll
                    for (int j = 0; j < 4; j++)
                        spart[(r * 16 + hg * 4 + j) * 68 + e2] = part[j];
                }
            }
        }
        __syncthreads();            // sync2: spart complete

        // ---- reduce 64 partials -> score per (r,h), all 512 threads ----
        {
            int rh = tid >> 2, q = tid & 3;
            const float4* pp = (const float4*)(spart + rh * 68 + q * 16);
            float4 v0 = pp[0], v1 = pp[1], v2 = pp[2], v3 = pp[3];
            float s = (((v0.x + v0.y) + (v0.z + v0.w)) + ((v1.x + v1.y) + (v1.z + v1.w))) +
                      (((v2.x + v2.y) + (v2.z + v2.w)) + ((v3.x + v3.y) + (v3.z + v3.w)));
            s += __shfl_xor_sync(0xffffffffu, s, 1);
            s += __shfl_xor_sync(0xffffffffu, s, 2);
            if (q == 0) sscore[rh >> 4][rh & 15] = s;
        }
        __syncthreads();            // sync3: sscore ready

        // ---- online softmax: warp w == head w (16 warps, all parallel) ----
        {
            int w = tid >> 5;       // 0..15 head
            int l = tid & 31;
            int r = l & 7;
            float s = sscore[r][w];
            bool act = (fl >> r) & 1;
            float sv = act ? s : -1e30f;
            float m0 = sm_m[w];
            float t = sv;
            t = fmaxf(t, __shfl_xor_sync(0xffffffffu, t, 1));
            t = fmaxf(t, __shfl_xor_sync(0xffffffffu, t, 2));
            t = fmaxf(t, __shfl_xor_sync(0xffffffffu, t, 4));   // max over r
            float nm = fmaxf(t, m0);
            float fac = exp2f((m0 - nm) * L2E);
            float wgt = act ? exp2f((s - nm) * L2E) : 0.f;
            float ws = wgt;
            ws += __shfl_xor_sync(0xffffffffu, ws, 1);
            ws += __shfl_xor_sync(0xffffffffu, ws, 2);
            ws += __shfl_xor_sync(0xffffffffu, ws, 4);
            if (l < 8) sw_[r][w] = wgt;
            if (l == 0) {
                sfac[w] = fac;
                sm_m[w] = nm;
                sm_d[w] = fmaf(fac, sm_d[w], ws);
            }
        }
        __syncthreads();            // sync4: sw_/sfac ready

        // ---- Phase B: rescale + weighted accumulate ----
        {
            float4 fv = *(const float4*)&sfac[hg * 4];
            u64 f2[4] = {pack2(fv.x, fv.x), pack2(fv.y, fv.y),
                         pack2(fv.z, fv.z), pack2(fv.w, fv.w)};
#pragma unroll
            for (int j = 0; j < 4; j++)
#pragma unroll
                for (int i = 0; i < 4; i++) ctx[j][i] = fmul2(ctx[j][i], f2[j]);

#pragma unroll
            for (int r = 0; r < RPB; r++) {
                if (!((fl >> r) & 1)) continue;
                float4 wv = *(const float4*)&sw_[r][hg * 4];
                u64 w2[4] = {pack2(wv.x, wv.x), pack2(wv.y, wv.y),
                             pack2(wv.z, wv.z), pack2(wv.w, wv.w)};
                const float4* xr = (const float4*)(xs + r * 1024 + eidx * 8);
                float4 xa = xr[0], xb = xr[1];
                u64 x0 = pack2(xa.x, xa.y), x1 = pack2(xa.z, xa.w);
                u64 x2 = pack2(xb.x, xb.y), x3 = pack2(xb.z, xb.w);
#pragma unroll
                for (int j = 0; j < 4; j++) {
                    ctx[j][0] = ffma2(w2[j], x0, ctx[j][0]);
                    ctx[j][1] = ffma2(w2[j], x1, ctx[j][1]);
                    ctx[j][2] = ffma2(w2[j], x2, ctx[j][2]);
                    ctx[j][3] = ffma2(w2[j], x3, ctx[j][3]);
                }
            }
        }
    }

    // epilogue: unnormalized ctx + per-chunk (m, d)
#pragma unroll
    for (int j = 0; j < 4; j++) {
        float* dst = g_ctxp + (((size_t)chunk * B_ + b) * H_ + hg * 4 + j) * E_ + eidx * 8;
        float x0, y0, x1, y1;
        unpack2(ctx[j][0], x0, y0);
        unpack2(ctx[j][1], x1, y1);
        ((float4*)dst)[0] = make_float4(x0, y0, x1, y1);
        unpack2(ctx[j][2], x0, y0);
        unpack2(ctx[j][3], x1, y1);
        ((float4*)dst)[1] = make_float4(x0, y0, x1, y1);
    }
    if (tid < H_) {
        g_m[(chunk * B_ + b) * H_ + tid] = sm_m[tid];
        g_d[(chunk * B_ + b) * H_ + tid] = sm_d[tid];
    }
}

// ---------------- K4: weighted combine + out = ctx@Wv + bv (1 b per block) ----------------
// grid (16 h, 32 b) block 256
__global__ void k_out(const float* __restrict__ Wv, const float* __restrict__ bv,
                      float* __restrict__ out) {
    int h = blockIdx.x;
    int b = blockIdx.y;
    int tid = threadIdx.x;
    int n = tid & 63;
    int qq = tid >> 6;

    __shared__ __align__(16) float sc[E_];
    __shared__ float smd[2][NC];
    __shared__ float swt[NC];

    if (tid < NC) {
        smd[0][tid] = g_m[(tid * B_ + b) * H_ + h];
        smd[1][tid] = g_d[(tid * B_ + b) * H_ + h];
    }
    __syncthreads();
    if (tid == 0) {
        float M = -1e30f;
#pragma unroll
        for (int c = 0; c < NC; c++) M = fmaxf(M, smd[0][c]);
        float Dn = 0.f;
        float t[NC];
#pragma unroll
        for (int c = 0; c < NC; c++) {
            float e = exp2f((smd[0][c] - M) * L2E);
            t[c] = e;
            Dn = fmaf(e, smd[1][c], Dn);
        }
        float invD = 1.0f / Dn;
#pragma unroll
        for (int c = 0; c < NC; c++) swt[c] = t[c] * invD;
    }
    __syncthreads();

    {
        float4 a = make_float4(0.f, 0.f, 0.f, 0.f);
#pragma unroll
        for (int c = 0; c < NC; c++) {
            float w = swt[c];
            float4 v = ((const float4*)(g_ctxp + (((size_t)c * B_ + b) * H_ + h) * E_))[tid];
            a.x = fmaf(w, v.x, a.x);
            a.y = fmaf(w, v.y, a.y);
            a.z = fmaf(w, v.z, a.z);
            a.w = fmaf(w, v.w, a.w);
        }
        ((float4*)sc)[tid] = a;
    }
    __syncthreads();

    int c = h * D_ + n;
    float acc = 0.f;
#pragma unroll 4
    for (int e = 0; e < 256; e++)
        acc = fmaf(sc[qq * 256 + e], Wv[(size_t)(qq * 256 + e) * E_ + c], acc);

    __shared__ float part[4][64];
    part[qq][n] = acc;
    __syncthreads();
    if (tid < 64)
        out[(size_t)b * E_ + h * D_ + tid] =
            ((part[0][tid] + part[1][tid]) + (part[2][tid] + part[3][tid])) + bv[h * D_ + tid];
}

// ---------------- launch ----------------
extern "C" void kernel_launch(void* const* d_in, const int* in_sizes, int n_in,
                              void* d_out, int out_size) {
    const float* seq1 = (const float*)d_in[0];
    const float* seq2 = (const float*)d_in[1];
    const int*   mask = (const int*)d_in[2];
    const float* Wq   = (const float*)d_in[3];
    const float* bq   = (const float*)d_in[4];
    const float* Wk   = (const float*)d_in[5];
    // d_in[6] = bk dropped (softmax-invariant uniform shift)
    const float* Wv   = (const float*)d_in[7];
    const float* bv   = (const float*)d_in[8];
    float* out = (float*)d_out;

    const int dynBytes = NST * RPB * 4096 + 128 * 68 * 4;   // 128KB + 34KB
    cudaFuncSetAttribute(k_fused, cudaFuncAttributeMaxDynamicSharedMemorySize, dynBytes);

    k_qproj<<<dim3(4, B_), 256>>>(seq1, Wq, bq);
    k_qk<<<dim3(H_, 16), 256>>>(Wk);
    k_pad<<<1, 32>>>();
    k_fused<<<dim3(NC, B_), 512, dynBytes>>>(seq2, mask);
    k_out<<<dim3(H_, B_), 256>>>(Wv, bv, out);
}

// round 14
// speedup vs baseline: 2.1161x; 1.2089x over previous
#include <cuda_runtime.h>
#include <cstdint>
#include <cstddef>

#define B_ 32
#define S_ 4096
#define E_ 1024
#define H_ 16
#define D_ 64
#define NC 16            // chunks over s (256 rows each)
#define RPB 16           // rows per batch
#define NBAT 16          // 256 / RPB
#define SPR 1092         // spart row stride (floats): 1092 mod 32 = 4 -> conflict-free
#define L2E 1.4426950408889634f

// ---------------- static scratch ----------------
__device__ float g_q[B_ * E_];
__device__ float g_qk[B_ * H_ * E_];
__device__ float g_ctxp[(size_t)NC * B_ * H_ * E_];   // unnormalized ctx per chunk
__device__ float g_m[NC * B_ * H_];
__device__ float g_d[NC * B_ * H_];

typedef unsigned long long u64;

__device__ __forceinline__ u64 pack2(float x, float y) {
    u64 p;
    asm("mov.b64 %0, {%1, %2};" : "=l"(p) : "f"(x), "f"(y));
    return p;
}
__device__ __forceinline__ void unpack2(u64 p, float& x, float& y) {
    asm("mov.b64 {%0, %1}, %2;" : "=f"(x), "=f"(y) : "l"(p));
}
__device__ __forceinline__ u64 ffma2(u64 a, u64 b, u64 c) {
    u64 d;
    asm("fma.rn.f32x2 %0, %1, %2, %3;" : "=l"(d) : "l"(a), "l"(b), "l"(c));
    return d;
}
__device__ __forceinline__ u64 fmul2(u64 a, u64 b) {
    u64 d;
    asm("mul.rn.f32x2 %0, %1, %2;" : "=l"(d) : "l"(a), "l"(b));
    return d;
}
__device__ __forceinline__ void cp16(uint32_t dst_smem, const void* src) {
    asm volatile("cp.async.cg.shared.global [%0], [%1], 16;" :: "r"(dst_smem), "l"(src));
}
__device__ __forceinline__ void cp_commit() { asm volatile("cp.async.commit_group;"); }
template <int N>
__device__ __forceinline__ void cp_wait() { asm volatile("cp.async.wait_group %0;" :: "n"(N)); }

// ---------------- K1: q = seq1@Wq + bq  (1 b per block) ----------------
// grid (4 jt, 32 b) block 256
__global__ void k_qproj(const float* __restrict__ seq1, const float* __restrict__ Wq,
                        const float* __restrict__ bq) {
    int b = blockIdx.y;
    int j = blockIdx.x * 256 + threadIdx.x;
    __shared__ __align__(16) float s1[E_];
    ((float4*)s1)[threadIdx.x] = ((const float4*)(seq1 + (size_t)b * E_))[threadIdx.x];
    __syncthreads();
    float a[8] = {0.f, 0.f, 0.f, 0.f, 0.f, 0.f, 0.f, 0.f};
#pragma unroll 4
    for (int e = 0; e < E_; e += 8) {
#pragma unroll
        for (int i = 0; i < 8; i++)
            a[i] = fmaf(s1[e + i], Wq[(size_t)(e + i) * E_ + j], a[i]);
    }
    float s = ((a[0] + a[1]) + (a[2] + a[3])) + ((a[4] + a[5]) + (a[6] + a[7]));
    g_q[b * E_ + j] = s + bq[j];
}

// ---------------- K2: qk[b][h][e] = (Σ_d q[b][h*64+d]·Wk[e][h*64+d]) * 0.125 ----------------
// grid (16 h, 16 et) block 256: thread = e_local(64) x bg(4, 8 b each)
__global__ void k_qk(const float* __restrict__ Wk) {
    int h = blockIdx.x;
    int e = blockIdx.y * 64 + (threadIdx.x & 63);
    int bg = threadIdx.x >> 6;
    __shared__ __align__(16) float2 sq[B_][D_ / 2];
    for (int i = threadIdx.x; i < B_ * (D_ / 2); i += 256) {
        int b = i >> 5, dp = i & 31;
        sq[b][dp] = ((const float2*)(g_q + b * E_ + h * D_))[dp];
    }
    __syncthreads();
    float2 wk[D_ / 2];
    const float2* wrow = (const float2*)(Wk + (size_t)e * E_ + h * D_);
#pragma unroll
    for (int i = 0; i < D_ / 2; i++) wk[i] = wrow[i];
#pragma unroll
    for (int bb = 0; bb < 8; bb++) {
        int b = bg * 8 + bb;
        float ax = 0.f, ay = 0.f;
#pragma unroll
        for (int i = 0; i < D_ / 2; i++) {
            float2 qv = sq[b][i];
            ax = fmaf(wk[i].x, qv.x, ax);
            ay = fmaf(wk[i].y, qv.y, ay);
        }
        g_qk[(b * H_ + h) * E_ + e] = (ax + ay) * 0.125f;
    }
}

// ---------------- pad kernel (keeps ncu sample index on k_fused) ----------------
__global__ void k_pad() {}

// ---------------- K3: fused scores + online softmax + ctx ----------------
// grid (NC, B_) block 512
// thread: hg = tid&3 (heads hg*4+j), eidx = tid>>2 (8 floats at eidx*8)
// dyn smem: sx[2][RPB][1024] 128KB (ping-pong) + spart[16 r][SPR] ~70KB
__global__ void __launch_bounds__(512, 1) k_fused(const float* __restrict__ seq2,
                                                  const int* __restrict__ mask) {
    extern __shared__ __align__(16) char dyn[];
    float* sx = (float*)dyn;                      // [2][16][1024]
    float* spart = (float*)(dyn + 131072);        // idx = r*SPR + h*68 + e2
    __shared__ __align__(16) float sw_[RPB][H_];
    __shared__ __align__(16) float sfac[H_];
    __shared__ float sm_m[H_], sm_d[H_];
    __shared__ uint32_t sball[8];

    int b = blockIdx.y;
    int chunk = blockIdx.x;
    int s0 = chunk * 256;
    int tid = threadIdx.x;
    int hg = tid & 3;
    int eidx = tid >> 2;            // 0..127, slice = 8 floats at eidx*8

    if (tid < 256) {
        int mm = mask[b * S_ + s0 + tid];
        uint32_t bal = __ballot_sync(0xffffffffu, mm != 0);
        if ((tid & 31) == 0) sball[tid >> 5] = bal;
    }
    if (tid < H_) { sm_m[tid] = -1e30f; sm_d[tid] = 0.f; }

    // qk regs: 4 heads x 8 e-floats (4 f32x2 each)
    u64 qk2[4][4];
#pragma unroll
    for (int j = 0; j < 4; j++) {
        const float4* p = (const float4*)(g_qk + ((size_t)b * H_ + hg * 4 + j) * E_ + eidx * 8);
        float4 v0 = p[0], v1 = p[1];
        qk2[j][0] = pack2(v0.x, v0.y);
        qk2[j][1] = pack2(v0.z, v0.w);
        qk2[j][2] = pack2(v1.x, v1.y);
        qk2[j][3] = pack2(v1.z, v1.w);
    }

    u64 ctx[4][4];
#pragma unroll
    for (int j = 0; j < 4; j++)
#pragma unroll
        for (int i = 0; i < 4; i++) ctx[j][i] = pack2(0.f, 0.f);

    uint32_t sx_addr = (uint32_t)__cvta_generic_to_shared(sx);
    const float* base = seq2 + ((size_t)b * S_ + s0) * E_;
    int r0 = tid >> 6;              // 0..7 staging row base
    int scol = tid & 63;            // 64 threads per row, 16 floats each

    __syncthreads();                // sball/sm_* visible

    // ---- staging: batch nb -> slot nb&1 (coalesced: lane stride 16B within k) ----
    auto stage = [&](int nb) {
        uint32_t flN = (sball[nb >> 1] >> ((nb & 1) * 16)) & 0xFFFFu;
        uint32_t slotOff = (uint32_t)(nb & 1) * 65536u;
#pragma unroll
        for (int h2 = 0; h2 < 2; h2++) {
            int row = h2 * 8 + r0;
            if ((flN >> row) & 1) {
                const float* src = base + ((size_t)nb * RPB + row) * E_ + scol * 4;
                uint32_t dst = sx_addr + slotOff + (uint32_t)row * 4096 + scol * 16;
#pragma unroll
                for (int k = 0; k < 4; k++) cp16(dst + k * 1024, src + k * 256);
            }
        }
        cp_commit();
    };

    stage(0);
    stage(1);

    for (int bat = 0; bat < NBAT; bat++) {
        cp_wait<1>();
        __syncthreads();            // sync1: batch `bat` (slot bat&1) ready

        uint32_t fl = (sball[bat >> 1] >> ((bat & 1) * 16)) & 0xFFFFu;
        const float* xs = sx + (bat & 1) * (RPB * 1024);

        // ---- Phase A: per-head partial dots ----
#pragma unroll
        for (int r = 0; r < RPB; r++) {
            if ((fl >> r) & 1) {
                const float4* xr = (const float4*)(xs + r * 1024 + eidx * 8);
                float4 xa = xr[0], xb = xr[1];
                u64 x0 = pack2(xa.x, xa.y), x1 = pack2(xa.z, xa.w);
                u64 x2 = pack2(xb.x, xb.y), x3 = pack2(xb.z, xb.w);
                float part[4];
#pragma unroll
                for (int j = 0; j < 4; j++) {
                    u64 a = fmul2(qk2[j][0], x0);
                    a = ffma2(qk2[j][1], x1, a);
                    a = ffma2(qk2[j][2], x2, a);
                    a = ffma2(qk2[j][3], x3, a);
                    float ax, ay;
                    unpack2(a, ax, ay);
                    part[j] = ax + ay;
                }
#pragma unroll
                for (int j = 0; j < 4; j++)
                    part[j] += __shfl_xor_sync(0xffffffffu, part[j], 4);
                if ((tid & 4) == 0) {       // even eidx writes combined pair
                    int e2 = eidx >> 1;     // 0..63
#pragma unroll
                    for (int j = 0; j < 4; j++)
                        spart[r * SPR + (hg * 4 + j) * 68 + e2] = part[j];
                }
            }
        }
        __syncthreads();            // sync2: spart complete

        // ---- merged reduce + online softmax: warp w == head w ----
        {
            int h = tid >> 5;       // 0..15 head
            int l = tid & 31;
            int r = l & 15;         // row
            int q = l >> 4;         // half of the 64 partials
            const float4* pb = (const float4*)(spart + r * SPR + h * 68 + q * 32);
            float4 v0 = pb[0], v1 = pb[1], v2 = pb[2], v3 = pb[3];
            float4 v4 = pb[4], v5 = pb[5], v6 = pb[6], v7 = pb[7];
            float s = ((((v0.x + v0.y) + (v0.z + v0.w)) + ((v1.x + v1.y) + (v1.z + v1.w))) +
                       (((v2.x + v2.y) + (v2.z + v2.w)) + ((v3.x + v3.y) + (v3.z + v3.w)))) +
                      ((((v4.x + v4.y) + (v4.z + v4.w)) + ((v5.x + v5.y) + (v5.z + v5.w))) +
                       (((v6.x + v6.y) + (v6.z + v6.w)) + ((v7.x + v7.y) + (v7.z + v7.w))));
            s += __shfl_xor_sync(0xffffffffu, s, 16);      // full score(r,h)
            bool act = (fl >> r) & 1;
            float sv = act ? s : -1e30f;
            float m0 = sm_m[h];
            float t = sv;
            t = fmaxf(t, __shfl_xor_sync(0xffffffffu, t, 1));
            t = fmaxf(t, __shfl_xor_sync(0xffffffffu, t, 2));
            t = fmaxf(t, __shfl_xor_sync(0xffffffffu, t, 4));
            t = fmaxf(t, __shfl_xor_sync(0xffffffffu, t, 8));   // max over 16 rows
            float nm = fmaxf(t, m0);
            float fac = exp2f((m0 - nm) * L2E);
            float wgt = act ? exp2f((s - nm) * L2E) : 0.f;
            float ws = wgt;
            ws += __shfl_xor_sync(0xffffffffu, ws, 1);
            ws += __shfl_xor_sync(0xffffffffu, ws, 2);
            ws += __shfl_xor_sync(0xffffffffu, ws, 4);
            ws += __shfl_xor_sync(0xffffffffu, ws, 8);          // sum over 16 rows
            if (l < 16) sw_[r][h] = wgt;
            if (l == 0) {
                sfac[h] = fac;
                sm_m[h] = nm;
                sm_d[h] = fmaf(fac, sm_d[h], ws);
            }
        }
        __syncthreads();            // sync3: sw_/sfac ready

        // ---- Phase B: rescale + weighted accumulate ----
        {
            float4 fv = *(const float4*)&sfac[hg * 4];
            u64 f2[4] = {pack2(fv.x, fv.x), pack2(fv.y, fv.y),
                         pack2(fv.z, fv.z), pack2(fv.w, fv.w)};
#pragma unroll
            for (int j = 0; j < 4; j++)
#pragma unroll
                for (int i = 0; i < 4; i++) ctx[j][i] = fmul2(ctx[j][i], f2[j]);

#pragma unroll
            for (int r = 0; r < RPB; r++) {
                if (!((fl >> r) & 1)) continue;
                float4 wv = *(const float4*)&sw_[r][hg * 4];
                u64 w2[4] = {pack2(wv.x, wv.x), pack2(wv.y, wv.y),
                             pack2(wv.z, wv.z), pack2(wv.w, wv.w)};
                const float4* xr = (const float4*)(xs + r * 1024 + eidx * 8);
                float4 xa = xr[0], xb = xr[1];
                u64 x0 = pack2(xa.x, xa.y), x1 = pack2(xa.z, xa.w);
                u64 x2 = pack2(xb.x, xb.y), x3 = pack2(xb.z, xb.w);
#pragma unroll
                for (int j = 0; j < 4; j++) {
                    ctx[j][0] = ffma2(w2[j], x0, ctx[j][0]);
                    ctx[j][1] = ffma2(w2[j], x1, ctx[j][1]);
                    ctx[j][2] = ffma2(w2[j], x2, ctx[j][2]);
                    ctx[j][3] = ffma2(w2[j], x3, ctx[j][3]);
                }
            }
        }
        __syncthreads();            // sync4: slot (bat&1) fully consumed

        // issue bat+2 into the just-freed slot; commit ALWAYS (wait accounting)
        if (bat + 2 < NBAT) stage(bat + 2);
        else cp_commit();
    }

    // epilogue: unnormalized ctx + per-chunk (m, d)
#pragma unroll
    for (int j = 0; j < 4; j++) {
        float* dst = g_ctxp + (((size_t)chunk * B_ + b) * H_ + hg * 4 + j) * E_ + eidx * 8;
        float x0, y0, x1, y1;
        unpack2(ctx[j][0], x0, y0);
        unpack2(ctx[j][1], x1, y1);
        ((float4*)dst)[0] = make_float4(x0, y0, x1, y1);
        unpack2(ctx[j][2], x0, y0);
        unpack2(ctx[j][3], x1, y1);
        ((float4*)dst)[1] = make_float4(x0, y0, x1, y1);
    }
    if (tid < H_) {
        g_m[(chunk * B_ + b) * H_ + tid] = sm_m[tid];
        g_d[(chunk * B_ + b) * H_ + tid] = sm_d[tid];
    }
}

// ---------------- K4: weighted combine + out = ctx@Wv + bv (1 b per block) ----------------
// grid (16 h, 32 b) block 256
__global__ void k_out(const float* __restrict__ Wv, const float* __restrict__ bv,
                      float* __restrict__ out) {
    int h = blockIdx.x;
    int b = blockIdx.y;
    int tid = threadIdx.x;
    int n = tid & 63;
    int qq = tid >> 6;

    __shared__ __align__(16) float sc[E_];
    __shared__ float smd[2][NC];
    __shared__ float swt[NC];

    if (tid < NC) {
        smd[0][tid] = g_m[(tid * B_ + b) * H_ + h];
        smd[1][tid] = g_d[(tid * B_ + b) * H_ + h];
    }
    __syncthreads();
    if (tid == 0) {
        float M = -1e30f;
#pragma unroll
        for (int c = 0; c < NC; c++) M = fmaxf(M, smd[0][c]);
        float Dn = 0.f;
        float t[NC];
#pragma unroll
        for (int c = 0; c < NC; c++) {
            float e = exp2f((smd[0][c] - M) * L2E);
            t[c] = e;
            Dn = fmaf(e, smd[1][c], Dn);
        }
        float invD = 1.0f / Dn;
#pragma unroll
        for (int c = 0; c < NC; c++) swt[c] = t[c] * invD;
    }
    __syncthreads();

    {
        float4 a = make_float4(0.f, 0.f, 0.f, 0.f);
#pragma unroll
        for (int c = 0; c < NC; c++) {
            float w = swt[c];
            float4 v = ((const float4*)(g_ctxp + (((size_t)c * B_ + b) * H_ + h) * E_))[tid];
            a.x = fmaf(w, v.x, a.x);
            a.y = fmaf(w, v.y, a.y);
            a.z = fmaf(w, v.z, a.z);
            a.w = fmaf(w, v.w, a.w);
        }
        ((float4*)sc)[tid] = a;
    }
    __syncthreads();

    int c = h * D_ + n;
    float a[8] = {0.f, 0.f, 0.f, 0.f, 0.f, 0.f, 0.f, 0.f};
#pragma unroll 4
    for (int e = 0; e < 256; e += 8) {
#pragma unroll
        for (int i = 0; i < 8; i++)
            a[i] = fmaf(sc[qq * 256 + e + i], Wv[(size_t)(qq * 256 + e + i) * E_ + c], a[i]);
    }
    float acc = ((a[0] + a[1]) + (a[2] + a[3])) + ((a[4] + a[5]) + (a[6] + a[7]));

    __shared__ float part[4][64];
    part[qq][n] = acc;
    __syncthreads();
    if (tid < 64)
        out[(size_t)b * E_ + h * D_ + tid] =
            ((part[0][tid] + part[1][tid]) + (part[2][tid] + part[3][tid])) + bv[h * D_ + tid];
}

// ---------------- launch ----------------
extern "C" void kernel_launch(void* const* d_in, const int* in_sizes, int n_in,
                              void* d_out, int out_size) {
    const float* seq1 = (const float*)d_in[0];
    const float* seq2 = (const float*)d_in[1];
    const int*   mask = (const int*)d_in[2];
    const float* Wq   = (const float*)d_in[3];
    const float* bq   = (const float*)d_in[4];
    const float* Wk   = (const float*)d_in[5];
    // d_in[6] = bk dropped (softmax-invariant uniform shift)
    const float* Wv   = (const float*)d_in[7];
    const float* bv   = (const float*)d_in[8];
    float* out = (float*)d_out;

    const int dynBytes = 131072 + RPB * SPR * 4;   // 128KB ring + ~70KB spart
    cudaFuncSetAttribute(k_fused, cudaFuncAttributeMaxDynamicSharedMemorySize, dynBytes);

    k_qproj<<<dim3(4, B_), 256>>>(seq1, Wq, bq);
    k_qk<<<dim3(H_, 16), 256>>>(Wk);
    k_pad<<<1, 32>>>();
    k_fused<<<dim3(NC, B_), 512, dynBytes>>>(seq2, mask);
    k_out<<<dim3(H_, B_), 256>>>(Wv, bv, out);
}